// round 5
// baseline (speedup 1.0000x reference)
#include <cuda_runtime.h>

// Problem constants
#define B_      256
#define L_      2048
#define V_      8
#define NS_     5        // shapelets
#define BAG_    409
#define BAGP_   416      // padded (zero-filled) shapelet length in smem
#define SHIFT_  204
#define NB_     9        // windows
#define FEAT_   80       // 2*NS*V
#define NCLASS_ 10
#define BN_EPS_ 1e-5f
#define NACC_   54       // 9 sx2 + 45 cross
#define RSTRIDE_ 57      // padded reduction row stride (odd multiplier -> conflict-free)

// Scratch
__device__ float g_feat[B_ * FEAT_];
__device__ float g_stats[2 * FEAT_];   // [0:80) centered sums, [80:160) centered sumsq
__device__ float g_c[NS_ * V_];        // centering constant per (s,v)

#define RED_FLOATS_ (8 * 32 * RSTRIDE_)          // per-block reduction scratch
#define K1_DSMEM_   (RED_FLOATS_ * sizeof(float))

// ---------------------------------------------------------------------------
// Kernel 1: block = (8 batches, 1 v), one warp per (b,v).
// t vectorized: 3 float4 iterations (t<384) + scalar tail (25).
// ||x-s||^2 = sum(x^2) + sum(s^2) - 2*sum(x*s); shapelets in smem.
// Cross-lane reduction via smem transpose (no 54x5 shuffle butterfly).
// Epilogue also accumulates centered BN statistics via global atomics.
// ---------------------------------------------------------------------------
__global__ __launch_bounds__(256, 2)
void shapelet_feat_kernel(const float* __restrict__ x,
                          const float* __restrict__ shp,
                          float* __restrict__ feat,
                          float* __restrict__ stats,
                          float* __restrict__ cvec)
{
    extern __shared__ float red[];          // [8][32][RSTRIDE_]
    __shared__ float s_shp[NS_][BAGP_];
    __shared__ float s_ss2[NS_];

    const int tid  = threadIdx.x;
    const int warp = tid >> 5;
    const int lane = tid & 31;
    const int v  = blockIdx.x & 7;
    const int b  = (blockIdx.x >> 3) * 8 + warp;

    // Stage shapelets (zero-pad 409..415)
    for (int i = tid; i < NS_ * BAGP_; i += 256) {
        const int s = i / BAGP_;
        const int t = i - s * BAGP_;
        s_shp[s][t] = (t < BAG_) ? shp[s * (V_ * BAG_) + v * BAG_ + t] : 0.f;
    }
    __syncthreads();

    // ss2[s]: warps 0..4, one shapelet each
    if (warp < NS_) {
        float q = 0.f;
        for (int t = lane; t < BAG_; t += 32) {
            const float sv = s_shp[warp][t];
            q = fmaf(sv, sv, q);
        }
#pragma unroll
        for (int o = 16; o > 0; o >>= 1) q += __shfl_xor_sync(0xffffffffu, q, o);
        if (lane == 0) s_ss2[warp] = q;
    }

    // ---- main accumulation (nb split into groups of 5/4 to bound live regs) ----
    const float* __restrict__ xr = x + (size_t)b * (V_ * L_) + (size_t)v * L_;
    const float* __restrict__ xr4 = xr + 4 * lane;

    float c[NS_][NB_];
    float sx2[NB_];
#pragma unroll
    for (int s = 0; s < NS_; s++)
#pragma unroll
        for (int nb = 0; nb < NB_; nb++) c[s][nb] = 0.f;
#pragma unroll
    for (int nb = 0; nb < NB_; nb++) sx2[nb] = 0.f;

#pragma unroll
    for (int k = 0; k < 3; k++) {
        const int t0 = 128 * k + 4 * lane;

        // group 0: nb 0..4
        {
            float4 xv[5];
#pragma unroll
            for (int j = 0; j < 5; j++)
                xv[j] = *(const float4*)(xr4 + j * SHIFT_ + 128 * k);
#pragma unroll
            for (int j = 0; j < 5; j++) {
                sx2[j] = fmaf(xv[j].x, xv[j].x, sx2[j]);
                sx2[j] = fmaf(xv[j].y, xv[j].y, sx2[j]);
                sx2[j] = fmaf(xv[j].z, xv[j].z, sx2[j]);
                sx2[j] = fmaf(xv[j].w, xv[j].w, sx2[j]);
            }
#pragma unroll
            for (int s = 0; s < NS_; s++) {
                const float4 sw = *(const float4*)(&s_shp[s][t0]);
#pragma unroll
                for (int j = 0; j < 5; j++) {
                    c[s][j] = fmaf(xv[j].x, sw.x, c[s][j]);
                    c[s][j] = fmaf(xv[j].y, sw.y, c[s][j]);
                    c[s][j] = fmaf(xv[j].z, sw.z, c[s][j]);
                    c[s][j] = fmaf(xv[j].w, sw.w, c[s][j]);
                }
            }
        }
        // group 1: nb 5..8
        {
            float4 xv[4];
#pragma unroll
            for (int j = 0; j < 4; j++)
                xv[j] = *(const float4*)(xr4 + (5 + j) * SHIFT_ + 128 * k);
#pragma unroll
            for (int j = 0; j < 4; j++) {
                sx2[5 + j] = fmaf(xv[j].x, xv[j].x, sx2[5 + j]);
                sx2[5 + j] = fmaf(xv[j].y, xv[j].y, sx2[5 + j]);
                sx2[5 + j] = fmaf(xv[j].z, xv[j].z, sx2[5 + j]);
                sx2[5 + j] = fmaf(xv[j].w, xv[j].w, sx2[5 + j]);
            }
#pragma unroll
            for (int s = 0; s < NS_; s++) {
                const float4 sw = *(const float4*)(&s_shp[s][t0]);
#pragma unroll
                for (int j = 0; j < 4; j++) {
                    c[s][5 + j] = fmaf(xv[j].x, sw.x, c[s][5 + j]);
                    c[s][5 + j] = fmaf(xv[j].y, sw.y, c[s][5 + j]);
                    c[s][5 + j] = fmaf(xv[j].z, sw.z, c[s][5 + j]);
                    c[s][5 + j] = fmaf(xv[j].w, sw.w, c[s][5 + j]);
                }
            }
        }
    }

    // scalar tail: t = 384 + lane, valid for lane < 25
    {
        const int t = 384 + lane;
        const bool ok = (lane < 25);
        float xs[NB_];
#pragma unroll
        for (int nb = 0; nb < NB_; nb++)
            xs[nb] = ok ? xr[nb * SHIFT_ + t] : 0.f;
#pragma unroll
        for (int nb = 0; nb < NB_; nb++)
            sx2[nb] = fmaf(xs[nb], xs[nb], sx2[nb]);
#pragma unroll
        for (int s = 0; s < NS_; s++) {
            const float sv = s_shp[s][t];
#pragma unroll
            for (int nb = 0; nb < NB_; nb++)
                c[s][nb] = fmaf(xs[nb], sv, c[s][nb]);
        }
    }

    // ---- smem transpose reduction ----
    float* base = red + warp * (32 * RSTRIDE_);
    {
        float* my = base + lane * RSTRIDE_;
#pragma unroll
        for (int nb = 0; nb < NB_; nb++) my[nb] = sx2[nb];
#pragma unroll
        for (int s = 0; s < NS_; s++)
#pragma unroll
            for (int nb = 0; nb < NB_; nb++) my[NB_ + s * NB_ + nb] = c[s][nb];
    }
    __syncwarp();

    float tot0, tot1;
    if (lane < 27) {
        float a0 = 0.f, a1 = 0.f, b0 = 0.f, b1 = 0.f;
#pragma unroll
        for (int l = 0; l < 32; l += 2) {
            a0 += base[l * RSTRIDE_ + lane];
            a1 += base[(l + 1) * RSTRIDE_ + lane];
            b0 += base[l * RSTRIDE_ + lane + 27];
            b1 += base[(l + 1) * RSTRIDE_ + lane + 27];
        }
        tot0 = a0 + a1;
        tot1 = b0 + b1;
    }
    __syncwarp();
    if (lane < 27) {
        base[lane]      = tot0;
        base[lane + 27] = tot1;
    }
    __syncthreads();                         // also publishes s_ss2 to all warps

    // ---- epilogue: lanes 0..4 handle shapelet s = lane ----
    if (lane < NS_) {
        const int s = lane;
        const float ss2v = s_ss2[s];
        float dmin = 3.402823466e+38f;
        float dsum = 0.f;
#pragma unroll
        for (int nb = 0; nb < NB_; nb++) {
            const float sx2t = base[nb];
            const float ct   = base[NB_ + s * NB_ + nb];
            const float d2 = sx2t + ss2v - 2.f * ct;
            const float d  = sqrtf(fmaxf(d2, 0.f));
            dmin = fminf(dmin, d);
            dsum += d;
        }
        const float davg = dsum * (1.f / 9.f);
        const int f0 = s * V_ + v;
        const int f1 = NS_ * V_ + s * V_ + v;
        float* fout = feat + (size_t)b * FEAT_;
        fout[f0] = dmin;
        fout[f1] = davg;

        // centered BN statistics (center identical for all warps of this (s,v))
        const float cc = sqrtf(409.f + ss2v);
        const float m0 = dmin - cc;
        const float m1 = davg - cc;
        atomicAdd(stats + f0,          m0);
        atomicAdd(stats + FEAT_ + f0,  m0 * m0);
        atomicAdd(stats + f1,          m1);
        atomicAdd(stats + FEAT_ + f1,  m1 * m1);

        if (blockIdx.x < 8 && warp == 0)     // one writer per (s,v)
            cvec[s * V_ + v] = cc;
    }
}

// ---------------------------------------------------------------------------
// Kernel 2: BN-stat finish + BN-folded FC. One block per class, one thread
// per batch row. Each block redundantly derives scale/shift from g_stats.
// ---------------------------------------------------------------------------
__global__ __launch_bounds__(256, 8)
void fc_kernel(const float* __restrict__ feat,
               const float* __restrict__ stats,
               const float* __restrict__ cvec,
               const float* __restrict__ gamma,
               const float* __restrict__ beta,
               const float* __restrict__ w,
               const float* __restrict__ fb,
               float* __restrict__ out)
{
    const int c = blockIdx.x;
    const int tid = threadIdx.x;
    __shared__ float s_scale[FEAT_];
    __shared__ float s_shift[FEAT_];
    __shared__ float wp[FEAT_];
    __shared__ float cbias;

    if (tid < FEAT_) {
        const int f = tid;
        const float sum = stats[f];
        const float sq  = stats[FEAT_ + f];
        const float cc  = cvec[(f < 40) ? f : (f - 40)];
        const float mu_c = sum * (1.f / 256.f);
        const float var  = sq * (1.f / 256.f) - mu_c * mu_c;
        const float mu   = cc + mu_c;
        const float rstd = rsqrtf(var + BN_EPS_);
        const float sc   = gamma[f] * rstd;
        s_scale[f] = sc;
        s_shift[f] = beta[f] - mu * sc;
    }
    __syncthreads();

    if (tid < FEAT_)
        wp[tid] = w[c * FEAT_ + tid] * s_scale[tid];

    if (tid >= 128 && tid < 160) {
        const int lane = tid - 128;
        float a = 0.f;
        for (int f = lane; f < FEAT_; f += 32)
            a = fmaf(s_shift[f], w[c * FEAT_ + f], a);
#pragma unroll
        for (int o = 16; o > 0; o >>= 1) a += __shfl_xor_sync(0xffffffffu, a, o);
        if (lane == 0) cbias = a + fb[c];
    }
    __syncthreads();

    const float4* __restrict__ fr = (const float4*)(feat + tid * FEAT_);
    float acc = cbias;
#pragma unroll
    for (int i = 0; i < FEAT_ / 4; i++) {
        float4 xv = fr[i];
        acc = fmaf(xv.x, wp[4 * i + 0], acc);
        acc = fmaf(xv.y, wp[4 * i + 1], acc);
        acc = fmaf(xv.z, wp[4 * i + 2], acc);
        acc = fmaf(xv.w, wp[4 * i + 3], acc);
    }
    out[tid * NCLASS_ + c] = acc;
}

// ---------------------------------------------------------------------------
extern "C" void kernel_launch(void* const* d_in, const int* in_sizes, int n_in,
                              void* d_out, int out_size)
{
    const float* x     = (const float*)d_in[0];  // [256, 2048, 8]
    const float* shp   = (const float*)d_in[1];  // [1, 5, 8, 409, 1]
    const float* gamma = (const float*)d_in[2];  // [80]
    const float* beta  = (const float*)d_in[3];  // [80]
    const float* fcw   = (const float*)d_in[4];  // [10, 80]
    const float* fcb   = (const float*)d_in[5];  // [10]
    float* out = (float*)d_out;                  // [256, 10]

    float *feat = nullptr, *stats = nullptr, *cvec = nullptr;
    cudaGetSymbolAddress((void**)&feat,  g_feat);
    cudaGetSymbolAddress((void**)&stats, g_stats);
    cudaGetSymbolAddress((void**)&cvec,  g_c);

    static bool attr_set = false;
    if (!attr_set) {
        cudaFuncSetAttribute(shapelet_feat_kernel,
                             cudaFuncAttributeMaxDynamicSharedMemorySize,
                             (int)K1_DSMEM_);
        attr_set = true;
    }

    cudaMemsetAsync(stats, 0, 2 * FEAT_ * sizeof(float));
    shapelet_feat_kernel<<<256, 256, K1_DSMEM_>>>(x, shp, feat, stats, cvec);
    fc_kernel<<<NCLASS_, 256>>>(feat, stats, cvec, gamma, beta, fcw, fcb, out);
}

// round 7
// speedup vs baseline: 1.6552x; 1.6552x over previous
#include <cuda_runtime.h>

// Problem constants
#define B_      256
#define L_      2048
#define V_      8
#define NS_     5        // shapelets
#define BAG_    409
#define BAGP_   416      // padded (zero-filled) shapelet length in smem
#define SHIFT_  204
#define NB_     9        // windows
#define FEAT_   80       // 2*NS*V
#define NCLASS_ 10
#define BN_EPS_ 1e-5f
#define RSTRIDE_ 57      // padded reduction row stride (conflict-free)

// Scratch
__device__ float g_feat[B_ * FEAT_];
__device__ float g_scale[FEAT_];
__device__ float g_shift[FEAT_];

#define RED_FLOATS_ (8 * 32 * RSTRIDE_)          // per-block reduction scratch
#define K1_DSMEM_   (RED_FLOATS_ * sizeof(float))

// ---------------------------------------------------------------------------
// Kernel 1: block = (8 batches, 1 v), one warp per (b,v).
// t vectorized: 3 float4 iterations (t<384) + scalar tail (25).
// ||x-s||^2 = sum(x^2) + sum(s^2) - 2*sum(x*s); shapelets in smem.
// Cross-lane reduction via smem transpose (no 54x5 shuffle butterfly).
// nb-dimension processed in two register groups (5+4) to avoid spills.
// ---------------------------------------------------------------------------
__global__ __launch_bounds__(256, 2)
void shapelet_feat_kernel(const float* __restrict__ x,
                          const float* __restrict__ shp,
                          float* __restrict__ feat)
{
    extern __shared__ float red[];          // [8][32][RSTRIDE_]
    __shared__ float s_shp[NS_][BAGP_];
    __shared__ float s_ss2[NS_];

    const int tid  = threadIdx.x;
    const int warp = tid >> 5;
    const int lane = tid & 31;
    const int v  = blockIdx.x & 7;
    const int b  = (blockIdx.x >> 3) * 8 + warp;

    // Stage shapelets (zero-pad 409..415)
    for (int i = tid; i < NS_ * BAGP_; i += 256) {
        const int s = i / BAGP_;
        const int t = i - s * BAGP_;
        s_shp[s][t] = (t < BAG_) ? shp[s * (V_ * BAG_) + v * BAG_ + t] : 0.f;
    }
    __syncthreads();

    // ss2[s]: warps 0..4, one shapelet each
    if (warp < NS_) {
        float q = 0.f;
        for (int t = lane; t < BAG_; t += 32) {
            const float sv = s_shp[warp][t];
            q = fmaf(sv, sv, q);
        }
#pragma unroll
        for (int o = 16; o > 0; o >>= 1) q += __shfl_xor_sync(0xffffffffu, q, o);
        if (lane == 0) s_ss2[warp] = q;
    }

    // ---- main accumulation (nb split into groups of 5/4 to bound live regs) ----
    const float* __restrict__ xr = x + (size_t)b * (V_ * L_) + (size_t)v * L_;
    const float* __restrict__ xr4 = xr + 4 * lane;

    float c[NS_][NB_];
    float sx2[NB_];
#pragma unroll
    for (int s = 0; s < NS_; s++)
#pragma unroll
        for (int nb = 0; nb < NB_; nb++) c[s][nb] = 0.f;
#pragma unroll
    for (int nb = 0; nb < NB_; nb++) sx2[nb] = 0.f;

#pragma unroll
    for (int k = 0; k < 3; k++) {
        const int t0 = 128 * k + 4 * lane;

        // group 0: nb 0..4
        {
            float4 xv[5];
#pragma unroll
            for (int j = 0; j < 5; j++)
                xv[j] = *(const float4*)(xr4 + j * SHIFT_ + 128 * k);
#pragma unroll
            for (int j = 0; j < 5; j++) {
                sx2[j] = fmaf(xv[j].x, xv[j].x, sx2[j]);
                sx2[j] = fmaf(xv[j].y, xv[j].y, sx2[j]);
                sx2[j] = fmaf(xv[j].z, xv[j].z, sx2[j]);
                sx2[j] = fmaf(xv[j].w, xv[j].w, sx2[j]);
            }
#pragma unroll
            for (int s = 0; s < NS_; s++) {
                const float4 sw = *(const float4*)(&s_shp[s][t0]);
#pragma unroll
                for (int j = 0; j < 5; j++) {
                    c[s][j] = fmaf(xv[j].x, sw.x, c[s][j]);
                    c[s][j] = fmaf(xv[j].y, sw.y, c[s][j]);
                    c[s][j] = fmaf(xv[j].z, sw.z, c[s][j]);
                    c[s][j] = fmaf(xv[j].w, sw.w, c[s][j]);
                }
            }
        }
        // group 1: nb 5..8
        {
            float4 xv[4];
#pragma unroll
            for (int j = 0; j < 4; j++)
                xv[j] = *(const float4*)(xr4 + (5 + j) * SHIFT_ + 128 * k);
#pragma unroll
            for (int j = 0; j < 4; j++) {
                sx2[5 + j] = fmaf(xv[j].x, xv[j].x, sx2[5 + j]);
                sx2[5 + j] = fmaf(xv[j].y, xv[j].y, sx2[5 + j]);
                sx2[5 + j] = fmaf(xv[j].z, xv[j].z, sx2[5 + j]);
                sx2[5 + j] = fmaf(xv[j].w, xv[j].w, sx2[5 + j]);
            }
#pragma unroll
            for (int s = 0; s < NS_; s++) {
                const float4 sw = *(const float4*)(&s_shp[s][t0]);
#pragma unroll
                for (int j = 0; j < 4; j++) {
                    c[s][5 + j] = fmaf(xv[j].x, sw.x, c[s][5 + j]);
                    c[s][5 + j] = fmaf(xv[j].y, sw.y, c[s][5 + j]);
                    c[s][5 + j] = fmaf(xv[j].z, sw.z, c[s][5 + j]);
                    c[s][5 + j] = fmaf(xv[j].w, sw.w, c[s][5 + j]);
                }
            }
        }
    }

    // scalar tail: t = 384 + lane, valid for lane < 25
    {
        const int t = 384 + lane;
        const bool ok = (lane < 25);
        float xs[NB_];
#pragma unroll
        for (int nb = 0; nb < NB_; nb++)
            xs[nb] = ok ? xr[nb * SHIFT_ + t] : 0.f;
#pragma unroll
        for (int nb = 0; nb < NB_; nb++)
            sx2[nb] = fmaf(xs[nb], xs[nb], sx2[nb]);
#pragma unroll
        for (int s = 0; s < NS_; s++) {
            const float sv = s_shp[s][t];
#pragma unroll
            for (int nb = 0; nb < NB_; nb++)
                c[s][nb] = fmaf(xs[nb], sv, c[s][nb]);
        }
    }

    // ---- smem transpose reduction ----
    float* base = red + warp * (32 * RSTRIDE_);
    {
        float* my = base + lane * RSTRIDE_;
#pragma unroll
        for (int nb = 0; nb < NB_; nb++) my[nb] = sx2[nb];
#pragma unroll
        for (int s = 0; s < NS_; s++)
#pragma unroll
            for (int nb = 0; nb < NB_; nb++) my[NB_ + s * NB_ + nb] = c[s][nb];
    }
    __syncwarp();

    float tot0, tot1;
    if (lane < 27) {
        float a0 = 0.f, a1 = 0.f, b0 = 0.f, b1 = 0.f;
#pragma unroll
        for (int l = 0; l < 32; l += 2) {
            a0 += base[l * RSTRIDE_ + lane];
            a1 += base[(l + 1) * RSTRIDE_ + lane];
            b0 += base[l * RSTRIDE_ + lane + 27];
            b1 += base[(l + 1) * RSTRIDE_ + lane + 27];
        }
        tot0 = a0 + a1;
        tot1 = b0 + b1;
    }
    __syncwarp();
    if (lane < 27) {
        base[lane]      = tot0;
        base[lane + 27] = tot1;
    }
    __syncthreads();                         // also publishes s_ss2 to all warps

    // ---- epilogue: lanes 0..4 handle shapelet s = lane ----
    if (lane < NS_) {
        const int s = lane;
        const float ss2v = s_ss2[s];
        float dmin = 3.402823466e+38f;
        float dsum = 0.f;
#pragma unroll
        for (int nb = 0; nb < NB_; nb++) {
            const float sx2t = base[nb];
            const float ct   = base[NB_ + s * NB_ + nb];
            const float d2 = sx2t + ss2v - 2.f * ct;
            const float d  = sqrtf(fmaxf(d2, 0.f));
            dmin = fminf(dmin, d);
            dsum += d;
        }
        float* fout = feat + (size_t)b * FEAT_;
        fout[s * V_ + v]            = dmin;
        fout[NS_ * V_ + s * V_ + v] = dsum * (1.f / 9.f);
    }
}

// ---------------------------------------------------------------------------
// Kernel 2a: BN batch stats (two-pass). One block per feature, one thread per
// batch row. Writes scale[f] = gamma*rstd, shift[f] = beta - mu*scale.
// ---------------------------------------------------------------------------
__global__ __launch_bounds__(256, 8)
void bn_stats_kernel(const float* __restrict__ feat,
                     const float* __restrict__ gamma,
                     const float* __restrict__ beta,
                     float* __restrict__ scale,
                     float* __restrict__ shift)
{
    const int f = blockIdx.x;
    const int tid = threadIdx.x;
    __shared__ float ws[8];
    __shared__ float wq[8];

    const float v = feat[tid * FEAT_ + f];

    float s = v;
#pragma unroll
    for (int o = 16; o > 0; o >>= 1) s += __shfl_xor_sync(0xffffffffu, s, o);
    if ((tid & 31) == 0) ws[tid >> 5] = s;
    __syncthreads();

    const float mu = (ws[0] + ws[1] + ws[2] + ws[3] +
                      ws[4] + ws[5] + ws[6] + ws[7]) * (1.f / 256.f);

    const float d = v - mu;
    float q = d * d;
#pragma unroll
    for (int o = 16; o > 0; o >>= 1) q += __shfl_xor_sync(0xffffffffu, q, o);
    if ((tid & 31) == 0) wq[tid >> 5] = q;
    __syncthreads();

    if (tid == 0) {
        const float var = (wq[0] + wq[1] + wq[2] + wq[3] +
                           wq[4] + wq[5] + wq[6] + wq[7]) * (1.f / 256.f);
        const float rstd = rsqrtf(var + BN_EPS_);
        const float sc = gamma[f] * rstd;
        scale[f] = sc;
        shift[f] = beta[f] - mu * sc;
    }
}

// ---------------------------------------------------------------------------
// Kernel 2b: FC with BN folded. One block per class, one thread per batch row.
// ---------------------------------------------------------------------------
__global__ __launch_bounds__(256, 8)
void fc_kernel(const float* __restrict__ feat,
               const float* __restrict__ scale,
               const float* __restrict__ shift,
               const float* __restrict__ w,
               const float* __restrict__ fb,
               float* __restrict__ out)
{
    const int c = blockIdx.x;
    const int b = threadIdx.x;
    __shared__ float wp[FEAT_];
    __shared__ float cbias;

    if (b < FEAT_)
        wp[b] = w[c * FEAT_ + b] * scale[b];

    if (b >= 128 && b < 160) {
        // warp 4 computes the folded bias: fb[c] + sum_f shift[f]*w[c,f]
        const int lane = b - 128;
        float a = 0.f;
        for (int f = lane; f < FEAT_; f += 32)
            a = fmaf(shift[f], w[c * FEAT_ + f], a);
#pragma unroll
        for (int o = 16; o > 0; o >>= 1) a += __shfl_xor_sync(0xffffffffu, a, o);
        if (lane == 0) cbias = a + fb[c];
    }
    __syncthreads();

    const float4* __restrict__ fr = (const float4*)(feat + b * FEAT_);
    float acc = cbias;
#pragma unroll
    for (int i = 0; i < FEAT_ / 4; i++) {
        float4 xv = fr[i];
        acc = fmaf(xv.x, wp[4 * i + 0], acc);
        acc = fmaf(xv.y, wp[4 * i + 1], acc);
        acc = fmaf(xv.z, wp[4 * i + 2], acc);
        acc = fmaf(xv.w, wp[4 * i + 3], acc);
    }
    out[b * NCLASS_ + c] = acc;
}

// ---------------------------------------------------------------------------
extern "C" void kernel_launch(void* const* d_in, const int* in_sizes, int n_in,
                              void* d_out, int out_size)
{
    const float* x     = (const float*)d_in[0];  // [256, 2048, 8]
    const float* shp   = (const float*)d_in[1];  // [1, 5, 8, 409, 1]
    const float* gamma = (const float*)d_in[2];  // [80]
    const float* beta  = (const float*)d_in[3];  // [80]
    const float* fcw   = (const float*)d_in[4];  // [10, 80]
    const float* fcb   = (const float*)d_in[5];  // [10]
    float* out = (float*)d_out;                  // [256, 10]

    float *feat = nullptr, *scale = nullptr, *shift = nullptr;
    cudaGetSymbolAddress((void**)&feat,  g_feat);
    cudaGetSymbolAddress((void**)&scale, g_scale);
    cudaGetSymbolAddress((void**)&shift, g_shift);

    static bool attr_set = false;
    if (!attr_set) {
        cudaFuncSetAttribute(shapelet_feat_kernel,
                             cudaFuncAttributeMaxDynamicSharedMemorySize,
                             (int)K1_DSMEM_);
        attr_set = true;
    }

    shapelet_feat_kernel<<<256, 256, K1_DSMEM_>>>(x, shp, feat);
    bn_stats_kernel<<<FEAT_, 256>>>(feat, gamma, beta, scale, shift);
    fc_kernel<<<NCLASS_, 256>>>(feat, scale, shift, fcw, fcb, out);
}